// round 3
// baseline (speedup 1.0000x reference)
#include <cuda_runtime.h>
#include <cstdint>

#define B_    8
#define N_    512
#define FIN   128
#define FOUT  64
#define ALPHA 0.2f
#define ROWS  4      // rows of i per block in pass2
#define NODES1 8     // nodes per block in pass1

// Scratch (allocation-free rule: __device__ globals)
__device__ float g_Wh[B_ * N_ * FOUT];   // 1 MB
__device__ float g_ei[B_ * N_];
__device__ float g_ej[B_ * N_];

// ---------------------------------------------------------------------------
// Pass 1: Wh = h @ W  (per (b,n): 64 outputs over K=128), plus
//         e_i[bn] = Wh[bn,:]·a[:64],  e_j[bn] = Wh[bn,:]·a[64:128]
// Grid: (B*N)/NODES1 = 512 blocks, 256 threads. W staged in smem (32 KB).
// ---------------------------------------------------------------------------
__global__ void __launch_bounds__(256) gat_pass1(
    const float* __restrict__ h,
    const float* __restrict__ W,
    const float* __restrict__ a)
{
    __shared__ float Ws[FIN * FOUT];       // 32 KB
    __shared__ float hs[NODES1][FIN];      // 4 KB
    __shared__ float red[NODES1 * 64];     // 2 KB

    const int tid  = threadIdx.x;
    const int base = blockIdx.x * NODES1;  // flattened b*N+n start

    // Stage W: 8192 floats = 2048 float4, 8 per thread
    {
        float4*       Wd   = reinterpret_cast<float4*>(Ws);
        const float4* Wsrc = reinterpret_cast<const float4*>(W);
#pragma unroll
        for (int q = 0; q < 8; q++) Wd[tid + 256 * q] = Wsrc[tid + 256 * q];
    }
    // Stage 8 rows of h: 1024 floats = 256 float4, 1 per thread
    reinterpret_cast<float4*>(&hs[0][0])[tid] =
        reinterpret_cast<const float4*>(h + (size_t)base * FIN)[tid];
    __syncthreads();

    const int o  = tid & 63;
    const int ng = tid >> 6;      // 0..3
    const int n0 = ng;            // node ng
    const int n1 = ng + 4;        // node ng+4

    float acc0 = 0.f, acc1 = 0.f;
#pragma unroll 8
    for (int i = 0; i < FIN; i++) {
        const float w = Ws[i * FOUT + o];
        acc0 += hs[n0][i] * w;
        acc1 += hs[n1][i] * w;
    }
    g_Wh[(size_t)(base + n0) * FOUT + o] = acc0;
    g_Wh[(size_t)(base + n1) * FOUT + o] = acc1;

    const float ai = a[o];
    const float aj = a[FOUT + o];

    // --- reduce e_i over o (tree in smem, both nodes per thread) ---
    red[n0 * 64 + o] = acc0 * ai;
    red[n1 * 64 + o] = acc1 * ai;
    __syncthreads();
#pragma unroll
    for (int s = 32; s >= 1; s >>= 1) {
        if (o < s) {
            red[n0 * 64 + o] += red[n0 * 64 + o + s];
            red[n1 * 64 + o] += red[n1 * 64 + o + s];
        }
        __syncthreads();
    }
    if (tid < NODES1) g_ei[base + tid] = red[tid * 64];
    __syncthreads();

    // --- reduce e_j over o ---
    red[n0 * 64 + o] = acc0 * aj;
    red[n1 * 64 + o] = acc1 * aj;
    __syncthreads();
#pragma unroll
    for (int s = 32; s >= 1; s >>= 1) {
        if (o < s) {
            red[n0 * 64 + o] += red[n0 * 64 + o + s];
            red[n1 * 64 + o] += red[n1 * 64 + o + s];
        }
        __syncthreads();
    }
    if (tid < NODES1) g_ej[base + tid] = red[tid * 64];
}

// ---------------------------------------------------------------------------
// Pass 2: per block: ROWS=4 rows i of one batch b.
//   scores  s[j] = edge_features[b,i,j,:]·U           (537 MB stream — the cost)
//   e       = e_i[i] + e_j[j] + a_e*s[j], leaky-relu, softmax over j
//   out[i,:] = sum_j attn[j] * Wh[b,j,:]  (Wh chunked through smem, shared by rows)
// Grid: B*N/ROWS = 1024 blocks, 256 threads.
// ---------------------------------------------------------------------------
__global__ void __launch_bounds__(256) gat_pass2(
    const float* __restrict__ ef,
    const float* __restrict__ U,
    const float* __restrict__ a,
    float* __restrict__ out)
{
    __shared__ float sc[ROWS][N_];        // 8 KB  scores -> probs
    __shared__ float whs[128][FOUT];      // 32 KB Wh chunk
    __shared__ float red[ROWS * 64];      // 1 KB

    const int blk = blockIdx.x;
    const int b   = blk / (N_ / ROWS);
    const int i0  = (blk % (N_ / ROWS)) * ROWS;

    const int tid  = threadIdx.x;
    const int lane = tid & 31;
    const int warp = tid >> 5;

    // ---------------- Phase 1: edge scores ----------------
    // warp pair per row; each warp handles 2 edges per iteration with float4.
    {
        const int r    = warp >> 1;
        const int half = warp & 1;
        const float4 u4 = reinterpret_cast<const float4*>(U)[lane & 15];
        const float4* ef4 = reinterpret_cast<const float4*>(
            ef + ((size_t)(b * N_ + i0 + r) * N_) * FOUT);
        // 256 edge-pairs per row, 2 warps -> 128 pairs per warp
#pragma unroll 4
        for (int p = half; p < N_ / 2; p += 2) {
            const float4 v = ef4[(size_t)p * 32 + lane];
            float d = v.x * u4.x + v.y * u4.y + v.z * u4.z + v.w * u4.w;
#pragma unroll
            for (int s = 8; s >= 1; s >>= 1)
                d += __shfl_xor_sync(0xFFFFFFFFu, d, s);
            if ((lane & 15) == 0) sc[r][2 * p + (lane >> 4)] = d;
        }
    }
    __syncthreads();

    // ---------------- Phase 2: e + leaky + softmax ----------------
    const int rr = tid >> 6;        // row 0..3
    const int k  = tid & 63;        // 64 threads per row
    const float ae  = a[2 * FOUT];
    const float eiv = g_ei[b * N_ + i0 + rr];

    float ev[8];
    float lmax = -1e30f;
#pragma unroll
    for (int m = 0; m < 8; m++) {
        const int j = k + 64 * m;
        float e = eiv + g_ej[b * N_ + j] + ae * sc[rr][j];
        e = (e >= 0.f) ? e : ALPHA * e;
        ev[m] = e;
        lmax  = fmaxf(lmax, e);
    }
    red[tid] = lmax;
    __syncthreads();
#pragma unroll
    for (int s = 32; s >= 1; s >>= 1) {
        if (k < s) red[tid] = fmaxf(red[tid], red[tid + s]);
        __syncthreads();
    }
    const float gmax = red[rr * 64];
    __syncthreads();

    float lsum = 0.f;
#pragma unroll
    for (int m = 0; m < 8; m++) {
        const float p = __expf(ev[m] - gmax);
        sc[rr][k + 64 * m] = p;
        lsum += p;
    }
    red[tid] = lsum;
    __syncthreads();
#pragma unroll
    for (int s = 32; s >= 1; s >>= 1) {
        if (k < s) red[tid] += red[tid + s];
        __syncthreads();
    }
    const float inv = 1.f / red[rr * 64];

    // ---------------- Phase 3: out = attn @ Wh (chunked through smem) -------
    float acc = 0.f;
    const float* WhB = g_Wh + (size_t)b * N_ * FOUT;
#pragma unroll 1
    for (int c = 0; c < 4; c++) {
        __syncthreads();   // protect whs from prior readers / red from writers
        const float4* src = reinterpret_cast<const float4*>(WhB + c * 128 * FOUT);
        float4*       dst = reinterpret_cast<float4*>(&whs[0][0]);
#pragma unroll
        for (int q = 0; q < 8; q++) dst[tid + 256 * q] = src[tid + 256 * q];
        __syncthreads();
#pragma unroll
        for (int jl = 0; jl < 128; jl++)
            acc += sc[rr][c * 128 + jl] * whs[jl][k];
    }
    out[(size_t)(b * N_ + i0 + rr) * FOUT + k] = acc * inv;
}

// ---------------------------------------------------------------------------
extern "C" void kernel_launch(void* const* d_in, const int* in_sizes, int n_in,
                              void* d_out, int out_size)
{
    const float* h  = (const float*)d_in[0];   // (8,512,128)
    const float* ef = (const float*)d_in[1];   // (8,512,512,64)
    const float* W  = (const float*)d_in[2];   // (1,128,64)
    const float* U  = (const float*)d_in[3];   // (1,64)
    const float* a  = (const float*)d_in[4];   // (1,129)
    float* out = (float*)d_out;                // (8,512,64)

    gat_pass1<<<(B_ * N_) / NODES1, 256>>>(h, W, a);
    gat_pass2<<<(B_ * N_) / ROWS, 256>>>(ef, U, a, out);
}

// round 5
// speedup vs baseline: 1.1467x; 1.1467x over previous
#include <cuda_runtime.h>
#include <cstdint>

#define B_    8
#define N_    512
#define FIN   128
#define FOUT  64
#define ALPHA 0.2f
#define ROWS  4      // rows of i per block in pass2
#define CHUNK 8      // edges per row per pipeline stage
#define NSTAGE 4     // cp.async pipeline depth
#define NODES1 8     // nodes per block in pass1

// Scratch (allocation-free rule: __device__ globals)
__device__ float g_Wh[B_ * N_ * FOUT];   // 1 MB
__device__ float g_ei[B_ * N_];
__device__ float g_ej[B_ * N_];

__device__ __forceinline__ uint32_t smem_u32(const void* p) {
    return (uint32_t)__cvta_generic_to_shared(p);
}
__device__ __forceinline__ void cp16(uint32_t dst, const void* src) {
    asm volatile("cp.async.cg.shared.global [%0], [%1], 16;\n" :: "r"(dst), "l"(src));
}
__device__ __forceinline__ void cp_commit() {
    asm volatile("cp.async.commit_group;\n" ::: "memory");
}
template <int n> __device__ __forceinline__ void cp_wait() {
    asm volatile("cp.async.wait_group %0;\n" :: "n"(n) : "memory");
}

// ---------------------------------------------------------------------------
// Pass 1 (unchanged from passing R2 version): Wh = h @ W, plus e_i / e_j.
// ---------------------------------------------------------------------------
__global__ void __launch_bounds__(256) gat_pass1(
    const float* __restrict__ h,
    const float* __restrict__ W,
    const float* __restrict__ a)
{
    __shared__ float Ws[FIN * FOUT];       // 32 KB
    __shared__ float hs[NODES1][FIN];      // 4 KB
    __shared__ float red[NODES1 * 64];     // 2 KB

    const int tid  = threadIdx.x;
    const int base = blockIdx.x * NODES1;

    {
        float4*       Wd   = reinterpret_cast<float4*>(Ws);
        const float4* Wsrc = reinterpret_cast<const float4*>(W);
#pragma unroll
        for (int q = 0; q < 8; q++) Wd[tid + 256 * q] = Wsrc[tid + 256 * q];
    }
    reinterpret_cast<float4*>(&hs[0][0])[tid] =
        reinterpret_cast<const float4*>(h + (size_t)base * FIN)[tid];
    __syncthreads();

    const int o  = tid & 63;
    const int ng = tid >> 6;
    const int n0 = ng;
    const int n1 = ng + 4;

    float acc0 = 0.f, acc1 = 0.f;
#pragma unroll 8
    for (int i = 0; i < FIN; i++) {
        const float w = Ws[i * FOUT + o];
        acc0 += hs[n0][i] * w;
        acc1 += hs[n1][i] * w;
    }
    g_Wh[(size_t)(base + n0) * FOUT + o] = acc0;
    g_Wh[(size_t)(base + n1) * FOUT + o] = acc1;

    const float ai = a[o];
    const float aj = a[FOUT + o];

    red[n0 * 64 + o] = acc0 * ai;
    red[n1 * 64 + o] = acc1 * ai;
    __syncthreads();
#pragma unroll
    for (int s = 32; s >= 1; s >>= 1) {
        if (o < s) {
            red[n0 * 64 + o] += red[n0 * 64 + o + s];
            red[n1 * 64 + o] += red[n1 * 64 + o + s];
        }
        __syncthreads();
    }
    if (tid < NODES1) g_ei[base + tid] = red[tid * 64];
    __syncthreads();

    red[n0 * 64 + o] = acc0 * aj;
    red[n1 * 64 + o] = acc1 * aj;
    __syncthreads();
#pragma unroll
    for (int s = 32; s >= 1; s >>= 1) {
        if (o < s) {
            red[n0 * 64 + o] += red[n0 * 64 + o + s];
            red[n1 * 64 + o] += red[n1 * 64 + o + s];
        }
        __syncthreads();
    }
    if (tid < NODES1) g_ej[base + tid] = red[tid * 64];
}

// ---------------------------------------------------------------------------
// Pass 2: cp.async-pipelined edge-feature stream + fused softmax + attn@Wh.
// Grid: B*N/ROWS = 1024 blocks, 256 threads. smem ~42 KB -> 5 blocks/SM.
// ---------------------------------------------------------------------------
__global__ void __launch_bounds__(256) gat_pass2(
    const float* __restrict__ ef,
    const float* __restrict__ U,
    const float* __restrict__ a,
    float* __restrict__ out)
{
    __shared__ float stg[NSTAGE][ROWS][CHUNK * FOUT]; // 32 KB (aliased as whs later)
    __shared__ float sc[ROWS][N_];                     // 8 KB scores -> probs
    __shared__ float red[256];                         // 1 KB

    const int blk = blockIdx.x;
    const int b   = blk / (N_ / ROWS);
    const int i0  = (blk % (N_ / ROWS)) * ROWS;

    const int tid  = threadIdx.x;
    const int lane = tid & 31;
    const int warp = tid >> 5;

    constexpr int NS         = N_ / CHUNK;              // 64 stages
    constexpr int STAGE_F4   = ROWS * CHUNK * FOUT / 4; // 512 float4 per stage
    constexpr int STAGE_BYTES = STAGE_F4 * 16;          // 8 KB

    // -------- per-thread copy descriptors (2 float4 per thread per stage) ---
    // flat f4 index f within a stage: row = f>>7, e = (f&127)>>4, k = f&15
    const float4* efb = reinterpret_cast<const float4*>(ef)
                        + ((size_t)(b * N_ + i0)) * N_ * 16;
    const int f0 = tid, f1 = tid + 256;
    const float4* src0 = efb + ((size_t)(f0 >> 7)) * (N_ * 16) + (f0 & 127);
    const float4* src1 = efb + ((size_t)(f1 >> 7)) * (N_ * 16) + (f1 & 127);
    const uint32_t d0 = smem_u32(&stg[0][0][0]) + f0 * 16;
    const uint32_t d1 = smem_u32(&stg[0][0][0]) + f1 * 16;

    // -------- pipeline prologue: issue stages 0..NSTAGE-2 -------------------
#pragma unroll
    for (int s = 0; s < NSTAGE - 1; s++) {
        const uint32_t boff = (uint32_t)(s & (NSTAGE - 1)) * STAGE_BYTES;
        cp16(d0 + boff, src0);
        cp16(d1 + boff, src1);
        src0 += CHUNK * 16;  // advance j0 by CHUNK edges (2 KB)
        src1 += CHUNK * 16;
        cp_commit();
    }

    // -------- main stream loop ----------------------------------------------
    {
        const float4 u4  = reinterpret_cast<const float4*>(U)[lane & 15];
        const int    row = warp >> 1;   // 2 warps per row

        for (int s = 0; s < NS; s++) {
            cp_wait<NSTAGE - 2>();
            __syncthreads();   // stage s visible to all; stage (s-1) buffer free

            const float* base = &stg[s & (NSTAGE - 1)][row][0];
#pragma unroll
            for (int p = 0; p < CHUNK / 4; p++) {
                const int g = (warp & 1) * (CHUNK / 4) + p;   // pair-group 0..3
                const float4 v = reinterpret_cast<const float4*>(base)[g * 32 + lane];
                float d = v.x * u4.x + v.y * u4.y + v.z * u4.z + v.w * u4.w;
                d += __shfl_xor_sync(0xFFFFFFFFu, d, 8);
                d += __shfl_xor_sync(0xFFFFFFFFu, d, 4);
                d += __shfl_xor_sync(0xFFFFFFFFu, d, 2);
                d += __shfl_xor_sync(0xFFFFFFFFu, d, 1);
                if ((lane & 15) == 0)
                    sc[row][s * CHUNK + 2 * g + (lane >> 4)] = d;
            }

            const int sn = s + NSTAGE - 1;
            if (sn < NS) {
                const uint32_t boff = (uint32_t)(sn & (NSTAGE - 1)) * STAGE_BYTES;
                cp16(d0 + boff, src0);
                cp16(d1 + boff, src1);
                src0 += CHUNK * 16;
                src1 += CHUNK * 16;
            }
            cp_commit();   // uniform group accounting (empty group near tail)
        }
        cp_wait<0>();
    }
    __syncthreads();

    // -------- softmax over j (leaky-relu + max/sum) -------------------------
    const int rr = tid >> 6;        // row 0..3
    const int k  = tid & 63;        // 64 threads per row
    const float ae  = a[2 * FOUT];
    const float eiv = g_ei[b * N_ + i0 + rr];

    float ev[8];
    float lmax = -1e30f;
#pragma unroll
    for (int m = 0; m < 8; m++) {
        const int j = k + 64 * m;
        float e = eiv + g_ej[b * N_ + j] + ae * sc[rr][j];
        e = (e >= 0.f) ? e : ALPHA * e;
        ev[m] = e;
        lmax  = fmaxf(lmax, e);
    }
    red[tid] = lmax;
    __syncthreads();
#pragma unroll
    for (int s = 32; s >= 1; s >>= 1) {
        if (k < s) red[tid] = fmaxf(red[tid], red[tid + s]);
        __syncthreads();
    }
    const float gmax = red[rr * 64];
    __syncthreads();

    float lsum = 0.f;
#pragma unroll
    for (int m = 0; m < 8; m++) {
        const float p = __expf(ev[m] - gmax);
        sc[rr][k + 64 * m] = p;
        lsum += p;
    }
    red[tid] = lsum;
    __syncthreads();
#pragma unroll
    for (int s = 32; s >= 1; s >>= 1) {
        if (k < s) red[tid] += red[tid + s];
        __syncthreads();
    }
    const float inv = 1.f / red[rr * 64];

    // -------- out = attn @ Wh (Wh chunked through smem, aliased on stg) -----
    float acc = 0.f;
    const float* WhB = g_Wh + (size_t)b * N_ * FOUT;
    float (*whs)[FOUT] = reinterpret_cast<float (*)[FOUT]>(&stg[0][0][0]); // 32 KB
#pragma unroll 1
    for (int c = 0; c < 4; c++) {
        __syncthreads();   // previous chunk fully consumed / red writers done
        const float4* src = reinterpret_cast<const float4*>(WhB + c * 128 * FOUT);
        float4*       dst = reinterpret_cast<float4*>(&whs[0][0]);
#pragma unroll
        for (int q = 0; q < 8; q++) dst[tid + 256 * q] = src[tid + 256 * q];
        __syncthreads();
        const float4* scv = reinterpret_cast<const float4*>(&sc[rr][c * 128]);
#pragma unroll 8
        for (int j4 = 0; j4 < 32; j4++) {
            const float4 s4 = scv[j4];
            acc += s4.x * whs[4 * j4 + 0][k];
            acc += s4.y * whs[4 * j4 + 1][k];
            acc += s4.z * whs[4 * j4 + 2][k];
            acc += s4.w * whs[4 * j4 + 3][k];
        }
    }
    out[(size_t)(b * N_ + i0 + rr) * FOUT + k] = acc * inv;
}

// ---------------------------------------------------------------------------
extern "C" void kernel_launch(void* const* d_in, const int* in_sizes, int n_in,
                              void* d_out, int out_size)
{
    const float* h  = (const float*)d_in[0];   // (8,512,128)
    const float* ef = (const float*)d_in[1];   // (8,512,512,64)
    const float* W  = (const float*)d_in[2];   // (1,128,64)
    const float* U  = (const float*)d_in[3];   // (1,64)
    const float* a  = (const float*)d_in[4];   // (1,129)
    float* out = (float*)d_out;                // (8,512,64)

    gat_pass1<<<(B_ * N_) / NODES1, 256>>>(h, W, a);
    gat_pass2<<<(B_ * N_) / ROWS, 256>>>(ef, U, a, out);
}